// round 4
// baseline (speedup 1.0000x reference)
#include <cuda_runtime.h>
#include <math.h>
#include <float.h>

#define N 256
#define DIM 128
#define RPB 4                 // rows (anchors) per block
#define NBLK (N / RPB)        // 64 blocks -> single wave
#define PST 9                 // float4 stride for partials (conflict-free)
#define FULL 0xffffffffu

__device__ float g_psum[NBLK];
__device__ float g_pcnt[NBLK];
__device__ unsigned int g_ticket = 0;   // reset by last block each launch

__global__ void __launch_bounds__(256, 1)
triplet_fused(const float* __restrict__ emb,
              const int*   __restrict__ lab32,
              float*       __restrict__ out) {
    __shared__ float4 part[N * PST];        // 36864 B; aliased as negd in phase 3
    __shared__ float4 sh_e4[RPB * 32];      // 4 anchor rows
    __shared__ float  normsh[N];            // |e_j|^2 for all j
    __shared__ float  Dmat[RPB * N];        // distances for this block's 4 rows
    __shared__ int    lab_sh[N];
    __shared__ unsigned short pairs[RPB * N];  // positive (r,k) pairs, 2KB
    __shared__ int    cnts[32], ofs[32];    // per-(r,warp) counts / offsets
    __shared__ int    np_sh;
    __shared__ float  wsum[8], wcnt[8];
    __shared__ int    sh_flag, sh_last;

    const int b = blockIdx.x;
    const int t = threadIdx.x;
    const int w = t >> 5, l = t & 31;

    if (t == 0) { sh_flag = 0; sh_last = 0; }
    __syncthreads();

    // int64 LE labels (values 0..15) have all-zero odd 32-bit words; int32 don't.
    // Words [0..255] are in-bounds for both layouts.
    if (t < 128 && lab32[2 * t + 1] != 0) sh_flag = 1;
    if (t < RPB * 32) {
        int r = t >> 5, c = t & 31;
        sh_e4[t] = reinterpret_cast<const float4*>(emb)[(b * RPB + r) * 32 + c];
    }
    __syncthreads();

    const bool is64 = (sh_flag == 0);
    lab_sh[t] = is64 ? lab32[2 * t] : lab32[t];

    // anchor chunks in registers (lane l holds chunk l of each anchor row)
    const float4 a0 = sh_e4[0 * 32 + l];
    const float4 a1 = sh_e4[1 * 32 + l];
    const float4 a2 = sh_e4[2 * 32 + l];
    const float4 a3 = sh_e4[3 * 32 + l];

    // ---- Phase 1: coalesced loads, 4 dots per load, split-K fold to 8 lanes.
    {
        const float4* E4 = reinterpret_cast<const float4*>(emb);
        const int jbase = w * 32;
#pragma unroll 4
        for (int jj = 0; jj < 32; ++jj) {
            const int j = jbase + jj;
            const float4 bv = E4[j * 32 + l];
            float d0 = bv.x*a0.x + bv.y*a0.y + bv.z*a0.z + bv.w*a0.w;
            float d1 = bv.x*a1.x + bv.y*a1.y + bv.z*a1.z + bv.w*a1.w;
            float d2 = bv.x*a2.x + bv.y*a2.y + bv.z*a2.z + bv.w*a2.w;
            float d3 = bv.x*a3.x + bv.y*a3.y + bv.z*a3.z + bv.w*a3.w;
            float np = bv.x*bv.x + bv.y*bv.y + bv.z*bv.z + bv.w*bv.w;
            d0 += __shfl_down_sync(FULL, d0, 16);  d0 += __shfl_down_sync(FULL, d0, 8);
            d1 += __shfl_down_sync(FULL, d1, 16);  d1 += __shfl_down_sync(FULL, d1, 8);
            d2 += __shfl_down_sync(FULL, d2, 16);  d2 += __shfl_down_sync(FULL, d2, 8);
            d3 += __shfl_down_sync(FULL, d3, 16);  d3 += __shfl_down_sync(FULL, d3, 8);
            np += __shfl_down_sync(FULL, np, 16);  np += __shfl_down_sync(FULL, np, 8);
            np += __shfl_down_sync(FULL, np, 4);   np += __shfl_down_sync(FULL, np, 2);
            np += __shfl_down_sync(FULL, np, 1);
            if (l < 8) part[j * PST + l] = make_float4(d0, d1, d2, d3);
            if (l == 0) normsh[j] = np;
        }
    }
    __syncthreads();

    // ---- Phase 2: thread t folds 8 partials -> 4 dots; compute D, pos masks.
    float4 s = part[t * PST + 0];
#pragma unroll
    for (int k = 1; k < 8; ++k) {
        float4 v = part[t * PST + k];
        s.x += v.x; s.y += v.y; s.z += v.z; s.w += v.w;
    }
    const float nt = normsh[t];
    const int labT = lab_sh[t];

    float Dr[RPB];
    bool  posr[RPB];
    unsigned bal[RPB];
    {
        const float dots[RPB] = { s.x, s.y, s.z, s.w };
#pragma unroll
        for (int r = 0; r < RPB; ++r) {
            const int i = b * RPB + r;
            const float D = sqrtf(fmaxf(normsh[i] + nt - 2.f * dots[r], 1e-4f));
            Dr[r] = D;
            Dmat[r * N + t] = D;
            posr[r] = (labT == lab_sh[i]) && (t != i);
            bal[r] = __ballot_sync(FULL, posr[r]);
            if (l == 0) cnts[r * 8 + w] = __popc(bal[r]);
        }
    }
    __syncthreads();   // all part reads done; cnts visible

    // negd aliases part
    float* negf = reinterpret_cast<float*>(part);
#pragma unroll
    for (int r = 0; r < RPB; ++r)
        negf[r * N + t] = posr[r] ? -FLT_MAX : Dr[r];

    // deterministic exclusive scan of the 32 (r,w) counts (warp 0)
    if (w == 0) {
        int x = cnts[l];
        const int v = x;
#pragma unroll
        for (int d = 1; d < 32; d <<= 1) {
            int y = __shfl_up_sync(FULL, x, d);
            if (l >= d) x += y;
        }
        ofs[l] = x - v;
        if (l == 31) np_sh = x;
    }
    __syncthreads();

    // write positive pairs at deterministic offsets
#pragma unroll
    for (int r = 0; r < RPB; ++r) {
        if (posr[r]) {
            int rank = __popc(bal[r] & ((1u << l) - 1u));
            pairs[ofs[r * 8 + w] + rank] = (unsigned short)((r << 8) | t);
        }
    }
    __syncthreads();

    // ---- Phase 3: one warp per positive pair; lanes scan 8 stride-32 elems.
    float lsum = 0.f, lcnt = 0.f;
    const int npair = np_sh;
    for (int p = w; p < npair; p += 8) {
        const unsigned pr = pairs[p];
        const int r = pr >> 8, k = pr & 255;
        const float Dk = Dmat[r * N + k];
        const float* nd = negf + r * N;
        float mx = -FLT_MAX, mn = FLT_MAX;
#pragma unroll
        for (int u = 0; u < 8; ++u) {
            float v = nd[u * 32 + l];
            mx = fmaxf(mx, v);
            mn = fminf(mn, v > Dk ? v : FLT_MAX);
        }
#pragma unroll
        for (int sft = 16; sft > 0; sft >>= 1) {
            mx = fmaxf(mx, __shfl_down_sync(FULL, mx, sft));
            mn = fminf(mn, __shfl_down_sync(FULL, mn, sft));
        }
        if (l == 0) {
            // semi-hard if a strictly-farther negative exists, else easiest neg
            float semi = (mn < FLT_MAX) ? (Dk - mn) : (Dk - mx);
            lsum += fmaxf(semi + 1.0f, 0.f);   // relu(semi + MARGIN)
            lcnt += 1.f;
        }
    }
    if (l == 0) { wsum[w] = lsum; wcnt[w] = lcnt; }
    __syncthreads();

    if (t == 0) {
        float S = 0.f, C = 0.f;
#pragma unroll
        for (int k = 0; k < 8; ++k) { S += wsum[k]; C += wcnt[k]; }
        g_psum[b] = S;
        g_pcnt[b] = C;
        __threadfence();
        unsigned tk = atomicAdd(&g_ticket, 1u);
        if (tk == NBLK - 1) {
            sh_last  = 1;
            g_ticket = 0;   // all blocks already added; safe for next replay
        }
    }
    __syncthreads();

    // ---- last block: reduce the 64 per-block partials (L1-bypass reads)
    if (sh_last) {
        float ss = 0.f, cc = 0.f;
        if (t < NBLK) { ss = __ldcg(&g_psum[t]); cc = __ldcg(&g_pcnt[t]); }
#pragma unroll
        for (int sft = 16; sft > 0; sft >>= 1) {
            ss += __shfl_down_sync(FULL, ss, sft);
            cc += __shfl_down_sync(FULL, cc, sft);
        }
        if (l == 0 && w < 2) { wsum[w] = ss; wcnt[w] = cc; }
        __syncthreads();
        if (t == 0)
            out[0] = (wsum[0] + wsum[1]) / (wcnt[0] + wcnt[1]);
    }
}

extern "C" void kernel_launch(void* const* d_in, const int* in_sizes, int n_in,
                              void* d_out, int out_size) {
    const float* emb  = (const float*)d_in[0];
    const int*   labs = (const int*)d_in[1];
    float* out = (float*)d_out;
    triplet_fused<<<NBLK, 256>>>(emb, labs, out);
}

// round 5
// speedup vs baseline: 1.4018x; 1.4018x over previous
#include <cuda_runtime.h>
#include <math.h>
#include <float.h>

#define N 256
#define RPB 2
#define NBLK (N / RPB)        // 128 blocks, single wave
#define FULL 0xffffffffu

__device__ float g_psum[NBLK];
__device__ float g_pcnt[NBLK];
__device__ unsigned int g_ticket = 0;   // reset by last block each launch

// Dynamic smem: full embedding matrix, 8192 float4 = 128KB, swizzled so that
// row-strided reads are bank-conflict-free: row j chunk c lives at j*32 + (c+j)%32.
extern __shared__ float4 sE[];

__global__ void __launch_bounds__(256, 1)
triplet_fused(const float* __restrict__ emb,
              const int*   __restrict__ lab32,
              float*       __restrict__ out) {
    __shared__ float  normsh[N];
    __shared__ float  Dmat[RPB * N];
    __shared__ float  negd[RPB * N];
    __shared__ int    lab_sh[N];
    __shared__ unsigned short pairs[RPB * N];
    __shared__ int    cnts[RPB * 8], ofs[RPB * 8];
    __shared__ int    np_sh;
    __shared__ float  wsum[8], wcnt[8];
    __shared__ int    sh_flag, sh_last;

    const int b = blockIdx.x;
    const int t = threadIdx.x;
    const int w = t >> 5, l = t & 31;

    if (t == 0) { sh_flag = 0; sh_last = 0; }
    __syncthreads();

    // int64 LE labels (0..15) have all-zero odd 32-bit words; int32 don't.
    // Words [0..255] are in-bounds for both layouts (>=1024B).
    if (t < 128 && lab32[2 * t + 1] != 0) sh_flag = 1;

    // ---- Stage all of E into smem (coalesced, MLP=32, swizzled store).
    const float4* E4 = reinterpret_cast<const float4*>(emb);
#pragma unroll 8
    for (int p = 0; p < 32; ++p) {
        const int g = p * 256 + t;          // global float4 index
        const int j = g >> 5, c = g & 31;   // row, chunk
        sE[(j << 5) + ((c + j) & 31)] = E4[g];
    }
    __syncthreads();

    const bool is64 = (sh_flag == 0);
    lab_sh[t] = is64 ? lab32[2 * t] : lab32[t];

    // ---- Phase 1: dot(e_t, anchors) + |e_t|^2, all from smem, no shuffles.
    const int i0 = b * RPB, i1 = i0 + 1;
    float d0a = 0.f, d0b = 0.f, d1a = 0.f, d1b = 0.f, na = 0.f, nb = 0.f;
    const float4* rowt = sE + (t  << 5);
    const float4* rowA = sE + (i0 << 5);
    const float4* rowB = sE + (i1 << 5);
#pragma unroll
    for (int c = 0; c < 32; c += 2) {
        float4 bv = rowt[(c + t)  & 31];        // conflict-free (swizzle)
        float4 a0 = rowA[(c + i0) & 31];        // uniform addr -> broadcast
        float4 a1 = rowB[(c + i1) & 31];
        d0a += bv.x*a0.x + bv.y*a0.y + bv.z*a0.z + bv.w*a0.w;
        d1a += bv.x*a1.x + bv.y*a1.y + bv.z*a1.z + bv.w*a1.w;
        na  += bv.x*bv.x + bv.y*bv.y + bv.z*bv.z + bv.w*bv.w;
        float4 bw = rowt[(c + 1 + t)  & 31];
        float4 b0 = rowA[(c + 1 + i0) & 31];
        float4 b1 = rowB[(c + 1 + i1) & 31];
        d0b += bw.x*b0.x + bw.y*b0.y + bw.z*b0.z + bw.w*b0.w;
        d1b += bw.x*b1.x + bw.y*b1.y + bw.z*b1.z + bw.w*b1.w;
        nb  += bw.x*bw.x + bw.y*bw.y + bw.z*bw.z + bw.w*bw.w;
    }
    const float nt = na + nb;
    normsh[t] = nt;
    __syncthreads();

    // ---- Distances, masks, deterministic pair compaction.
    const float dot0 = d0a + d0b, dot1 = d1a + d1b;
    const int labT = lab_sh[t];
    float Dr[RPB];
    Dr[0] = sqrtf(fmaxf(normsh[i0] + nt - 2.f * dot0, 1e-4f));
    Dr[1] = sqrtf(fmaxf(normsh[i1] + nt - 2.f * dot1, 1e-4f));
    bool posr[RPB];
    posr[0] = (labT == lab_sh[i0]) && (t != i0);
    posr[1] = (labT == lab_sh[i1]) && (t != i1);
    unsigned bal[RPB];
#pragma unroll
    for (int r = 0; r < RPB; ++r) {
        Dmat[r * N + t] = Dr[r];
        // negatives include t==i (reference keeps diagonal in (1-pos); d_ii=0.01)
        negd[r * N + t] = posr[r] ? -FLT_MAX : Dr[r];
        bal[r] = __ballot_sync(FULL, posr[r]);
        if (l == 0) cnts[r * 8 + w] = __popc(bal[r]);
    }
    __syncthreads();

    if (w == 0) {   // exclusive scan of 16 (r,warp) counts -> deterministic offsets
        int x = (l < RPB * 8) ? cnts[l] : 0;
        const int v = x;
#pragma unroll
        for (int d = 1; d < 32; d <<= 1) {
            int y = __shfl_up_sync(FULL, x, d);
            if (l >= d) x += y;
        }
        if (l < RPB * 8) ofs[l] = x - v;
        if (l == RPB * 8 - 1) np_sh = x;
    }
    __syncthreads();

#pragma unroll
    for (int r = 0; r < RPB; ++r)
        if (posr[r]) {
            int rank = __popc(bal[r] & ((1u << l) - 1u));
            pairs[ofs[r * 8 + w] + rank] = (unsigned short)((r << 8) | t);
        }
    __syncthreads();

    // ---- Phase 3: warp per pair, 2 pairs in flight per warp (ILP on shfl chains).
    float lsum = 0.f, lcnt = 0.f;
    const int npair = np_sh;
    for (int p = w; p < npair; p += 16) {
        const int pB = p + 8;
        const bool hasB = (pB < npair);
        const unsigned prA = pairs[p];
        const unsigned prB = pairs[hasB ? pB : p];
        const int rA = prA >> 8, kA = prA & 255;
        const int rB = prB >> 8, kB = prB & 255;
        const float DA = Dmat[rA * N + kA];
        const float DB = Dmat[rB * N + kB];
        const float* ndA = negd + rA * N;
        const float* ndB = negd + rB * N;
        float mxA = -FLT_MAX, mnA = FLT_MAX;
        float mxB = -FLT_MAX, mnB = FLT_MAX;
#pragma unroll
        for (int u = 0; u < 8; ++u) {
            float vA = ndA[u * 32 + l];
            float vB = ndB[u * 32 + l];
            mxA = fmaxf(mxA, vA);
            mnA = fminf(mnA, vA > DA ? vA : FLT_MAX);
            mxB = fmaxf(mxB, vB);
            mnB = fminf(mnB, vB > DB ? vB : FLT_MAX);
        }
#pragma unroll
        for (int s = 16; s > 0; s >>= 1) {
            mxA = fmaxf(mxA, __shfl_down_sync(FULL, mxA, s));
            mnA = fminf(mnA, __shfl_down_sync(FULL, mnA, s));
            mxB = fmaxf(mxB, __shfl_down_sync(FULL, mxB, s));
            mnB = fminf(mnB, __shfl_down_sync(FULL, mnB, s));
        }
        if (l == 0) {
            // semi-hard if a strictly-farther negative exists, else easiest neg
            float semiA = (mnA < FLT_MAX) ? (DA - mnA) : (DA - mxA);
            lsum += fmaxf(semiA + 1.0f, 0.f);   // relu(semi + MARGIN)
            lcnt += 1.f;
            if (hasB) {
                float semiB = (mnB < FLT_MAX) ? (DB - mnB) : (DB - mxB);
                lsum += fmaxf(semiB + 1.0f, 0.f);
                lcnt += 1.f;
            }
        }
    }
    if (l == 0) { wsum[w] = lsum; wcnt[w] = lcnt; }
    __syncthreads();

    if (t == 0) {
        float S = 0.f, C = 0.f;
#pragma unroll
        for (int k = 0; k < 8; ++k) { S += wsum[k]; C += wcnt[k]; }
        g_psum[b] = S;
        g_pcnt[b] = C;
        __threadfence();
        unsigned tk = atomicAdd(&g_ticket, 1u);
        if (tk == NBLK - 1) {
            sh_last  = 1;
            g_ticket = 0;   // all blocks already added; safe for next replay
        }
    }
    __syncthreads();

    // ---- Last block: reduce the 128 per-block partials (L1-bypass reads).
    if (sh_last) {
        float ss = 0.f, cc = 0.f;
        if (t < NBLK) { ss = __ldcg(&g_psum[t]); cc = __ldcg(&g_pcnt[t]); }
#pragma unroll
        for (int s = 16; s > 0; s >>= 1) {
            ss += __shfl_down_sync(FULL, ss, s);
            cc += __shfl_down_sync(FULL, cc, s);
        }
        if (l == 0) { wsum[w] = ss; wcnt[w] = cc; }
        __syncthreads();
        if (t == 0) {
            float S = 0.f, C = 0.f;
#pragma unroll
            for (int k = 0; k < 8; ++k) { S += wsum[k]; C += wcnt[k]; }
            out[0] = S / C;
        }
    }
}

extern "C" void kernel_launch(void* const* d_in, const int* in_sizes, int n_in,
                              void* d_out, int out_size) {
    const float* emb  = (const float*)d_in[0];
    const int*   labs = (const int*)d_in[1];
    float* out = (float*)d_out;
    // 128KB dynamic smem (allowed: attribute set, not an allocation)
    cudaFuncSetAttribute(triplet_fused,
                         cudaFuncAttributeMaxDynamicSharedMemorySize, 131072);
    triplet_fused<<<NBLK, 256, 131072>>>(emb, labs, out);
}